// round 11
// baseline (speedup 1.0000x reference)
#include <cuda_runtime.h>
#include <cuda_bf16.h>
#include <cstdint>

#define NN 2048
#define KK 4095              // number of anti-diagonals = 2N-1
#define BIGF 1e10f
#define C_EXP 14.4269504088896340f   /* 1/(gamma*ln2), gamma=0.1 */
#define GLN2  0.0693147180559945f    /* gamma*ln2 = 1/C_EXP */
#define BIGC  (BIGF * C_EXP)
#define DSK_STRIDE ((size_t)NN)
#define DSK_MAT ((size_t)KK * (size_t)NN)   // 8,386,560 floats per matrix

// ---------------- device scratch (no allocations allowed) ----------------
__device__ float  g_dsk[3 * KK * NN];   // ~100.6 MB, diagonal-major D for xy/xx/yy
__device__ float  g_norms[2 * NN];      // row norms of a (first 2048) and b (next 2048)
__device__ double g_idm[2];             // idm_a, idm_b accumulators
__device__ float  g_sdtw[3];            // softdtw(xy), softdtw(xx), softdtw(yy)

// ---------------- fast math helpers ----------------
__device__ __forceinline__ float ex2f(float x) {
    float y; asm("ex2.approx.ftz.f32 %0, %1;" : "=f"(y) : "f"(x)); return y;
}
__device__ __forceinline__ float lg2f_(float x) {
    float y; asm("lg2.approx.f32 %0, %1;" : "=f"(y) : "f"(x)); return y;
}
__device__ __forceinline__ uint32_t smem_u32(const void* p) {
    uint32_t a;
    asm("{ .reg .u64 t; cvta.to.shared.u64 t, %1; cvt.u32.u64 %0, t; }" : "=r"(a) : "l"(p));
    return a;
}

// ---------------- row norms + accumulator init ----------------
__global__ void norms_kernel(const float* __restrict__ a, const float* __restrict__ b) {
    if (blockIdx.x == 0 && threadIdx.x == 0) { g_idm[0] = 0.0; g_idm[1] = 0.0; }
    int w    = blockIdx.x * (blockDim.x >> 5) + (threadIdx.x >> 5);
    int lane = threadIdx.x & 31;
    if (w >= 2 * NN) return;
    const float* src = (w < NN) ? (a + (size_t)w * 128) : (b + (size_t)(w - NN) * 128);
    float s = 0.0f;
#pragma unroll
    for (int q = 0; q < 4; q++) { float v = src[lane + 32 * q]; s = fmaf(v, v, s); }
#pragma unroll
    for (int off = 16; off; off >>= 1) s += __shfl_xor_sync(0xffffffffu, s, off);
    if (lane == 0) g_norms[w] = s;
}

// ---------------- pairwise sqdist GEMM (R7 scalar version): diagonal-major D + fused idm ----------------
__global__ void __launch_bounds__(256) pairdist_kernel(const float* __restrict__ a,
                                                       const float* __restrict__ b) {
    __shared__ float pool[2 * 64 * 65];   // 33,280 B
    float* xsT = pool;                    // [kk][ii], stride 65 (conflict-free)
    float* ysT = pool + 64 * 65;

    const int z = blockIdx.z;             // 0: (a,b)  1: (a,a)  2: (b,b)
    const float* X  = (z == 2) ? b : a;
    const float* Y  = (z == 0) ? b : ((z == 1) ? a : b);
    const float* xn = g_norms + ((z == 2) ? NN : 0);
    const float* yn = g_norms + ((z == 1) ? 0 : NN);

    const int i0 = blockIdx.y * 64, j0 = blockIdx.x * 64;
    const int tid = threadIdx.x;
    const int tx = tid & 15, ty = tid >> 4;

    float acc[4][4];
#pragma unroll
    for (int r = 0; r < 4; r++)
#pragma unroll
        for (int c = 0; c < 4; c++) acc[r][c] = 0.0f;

    for (int kc = 0; kc < 128; kc += 64) {
        const int kk = tid & 63, ib = tid >> 6;
#pragma unroll
        for (int ii = ib; ii < 64; ii += 4) {
            xsT[kk * 65 + ii] = X[(size_t)(i0 + ii) * 128 + kc + kk];
            ysT[kk * 65 + ii] = Y[(size_t)(j0 + ii) * 128 + kc + kk];
        }
        __syncthreads();
#pragma unroll 4
        for (int k2 = 0; k2 < 64; ++k2) {
            float ra[4], rb[4];
#pragma unroll
            for (int r = 0; r < 4; r++) ra[r] = xsT[k2 * 65 + ty * 4 + r];
#pragma unroll
            for (int c = 0; c < 4; c++) rb[c] = ysT[k2 * 65 + tx * 4 + c];
#pragma unroll
            for (int r = 0; r < 4; r++)
#pragma unroll
                for (int c = 0; c < 4; c++) acc[r][c] = fmaf(ra[r], rb[c], acc[r][c]);
        }
        __syncthreads();
    }

    float xnv[4], ynv[4];
#pragma unroll
    for (int r = 0; r < 4; r++) xnv[r] = xn[i0 + ty * 4 + r];
#pragma unroll
    for (int c = 0; c < 4; c++) ynv[c] = yn[j0 + tx * 4 + c];

    float* ds = pool;                     // reuse; 64 x 66 floats
    float lsum = 0.0f;
    const float inv_n = 1.0f / 2048.0f;
    const float thr   = 10.0f / 2048.0f;  // SIGMA / seq_len (exact in fp32)
#pragma unroll
    for (int r = 0; r < 4; r++) {
#pragma unroll
        for (int c = 0; c < 4; c++) {
            float d = fmaxf(xnv[r] + ynv[c] - 2.0f * acc[r][c], 0.0f);
            ds[(ty * 4 + r) * 66 + tx * 4 + c] = d;
            if (z) {
                int ig = i0 + ty * 4 + r, jg = j0 + tx * 4 + c;
                float gd   = (float)(ig - jg) * inv_n;
                float wgt  = fmaf(gd, gd, 1.0f);
                float diff = fabsf(gd) - thr;
                float prob = fmaxf(2.0f - d, 0.0f);
                lsum += (diff > 0.0f) ? (wgt * prob) : d;
            }
        }
    }
    if (z) {
#pragma unroll
        for (int off = 16; off; off >>= 1) lsum += __shfl_xor_sync(0xffffffffu, lsum, off);
        if ((tid & 31) == 0) atomicAdd(&g_idm[z - 1], (double)lsum);
    }
    __syncthreads();  // ds fully written before diag write-out

    float* dst = g_dsk + (size_t)z * DSK_MAT + (size_t)(i0 + j0) * DSK_STRIDE + i0;
    const int w = tid >> 5, lane = tid & 31;
    for (int d = w; d < 127; d += 8) {
        int lo = max(0, d - 63), hi = min(63, d);
        for (int e = lo + lane; e <= hi; e += 32) {
            dst[(size_t)d * DSK_STRIDE + e] = ds[e * 66 + (d - e)];
        }
    }
}

// ---------------- softDTW: R7 wavefront scheme, log2-scaled state ----------------
// 3 clusters x 8 CTAs x 256 threads, 1 element/thread. State u = r * C_EXP.
#define PF 8
__global__ void __launch_bounds__(256, 1) __cluster_dims__(8, 1, 1)
softdtw_kernel() {
    const int bz   = blockIdx.x;
    const int z    = bz >> 3;            // matrix id
    const int rank = bz & 7;             // segment within cluster
    const float* __restrict__ dsk = g_dsk + (size_t)z * DSK_MAT;
    const int t = threadIdx.x;
    const int lane = t & 31, w = t >> 5;
    const int i = rank * 256 + t;        // global element index on each diagonal

    __shared__ unsigned long long inbox[4096];     // 32 KB, slot k: left CTA's u_{k-1}, tag=k
    __shared__ unsigned long long ring[7][256];    // 14 KB, boundary w -> w+1
    __shared__ unsigned int prog[8];               // consumer progress (for backpressure)

    for (int s = t; s < 4096; s += 256) inbox[s] = 0ULL;
    for (int s = t; s < 7 * 256; s += 256) ((unsigned long long*)ring)[s] = 0ULL;
    if (t < 8) prog[t] = 0u;
    __syncthreads();
    if (t == 0) {   // pre-publish diag-0 boundaries (u_0 at any boundary is BIGC)
        unsigned long long p0 = (1ULL << 32) | (unsigned long long)__float_as_uint(BIGC);
        for (int b = 0; b < 7; b++) ring[b][1] = p0;
    }
    __syncthreads();
    asm volatile("barrier.cluster.arrive.aligned;" ::: "memory");
    asm volatile("barrier.cluster.wait.aligned;" ::: "memory");

    const uint32_t inbox_a = smem_u32(inbox);
    const uint32_t ring_a  = smem_u32(ring);
    const uint32_t prog_a  = smem_u32(prog);
    uint32_t rem_inbox = 0;
    if (rank < 7) {
        asm("mapa.shared::cluster.u32 %0, %1, %2;"
            : "=r"(rem_inbox) : "r"(inbox_a), "r"(rank + 1));
    }
    if (t == 255 && rank < 7) {   // cross-CTA pre-publish of diag-0 boundary
        unsigned long long p0 = (1ULL << 32) | (unsigned long long)__float_as_uint(BIGC);
        asm volatile("st.shared::cluster.u64 [%0], %1;" :: "r"(rem_inbox + 8u), "l"(p0) : "memory");
    }

    const bool has_left  = (w > 0) || (rank > 0);
    const bool pub_ring  = (w < 7);
    const bool pub_dsmem = (w == 7) && (rank < 7);
    const uint32_t cons_base = (w == 0) ? inbox_a : (ring_a + (uint32_t)(w - 1) * 2048u);
    const uint32_t cons_mask = (w == 0) ? 0xFFFFFFFFu : 2047u;   // byte-offset mask
    const uint32_t prod_base = ring_a + (uint32_t)w * 2048u;     // valid when w<7
    const uint32_t myprog_a  = prog_a + 4u * (uint32_t)w;
    const uint32_t rprog_a   = prog_a + 4u * (uint32_t)(w + 1);

    // state (scaled by C_EXP): r1 = u_{k-1}[i]; shp = u_{k-2}[i-1]; prev_in = boundary u_{k-2}[i-1]
    float r1 = (i == 0) ? dsk[0] * C_EXP : BIGC;
    float shp = BIGC, prev_in = BIGC;

    // D prefetch ring (pre-scaled), depth PF; rotation renamed away under unrolling
    float dd[PF];
#pragma unroll
    for (int q = 0; q < PF; q++) {
        int kn = 1 + q;
        dd[q] = (kn <= KK - 1 && kn >= i && kn <= i + (NN - 1))
              ? dsk[(size_t)kn * NN + i] * C_EXP : BIGC;
    }
    const float* __restrict__ prow = dsk + (size_t)(1 + PF) * NN + i;

    auto body = [&](int k) {
        // prefetch diag k+PF (predicated, coalesced)
        const int kn = k + PF;
        float dn = BIGC;
        if (kn <= KK - 1) {
            if (kn >= i && kn <= i + (NN - 1)) dn = *prow * C_EXP;
        }
        prow += NN;

        // poll left boundary u_{k-1} (lane 0 only, warp-uniform result via select)
        float in1 = BIGC;
        if (has_left) {
            unsigned long long v;
            const uint32_t addr = cons_base + (((uint32_t)k * 8u) & cons_mask);
            do {
                asm volatile("ld.volatile.shared.u64 %0, [%1];" : "=l"(v) : "r"(addr));
            } while ((unsigned)(v >> 32) != (unsigned)k);
            in1 = __uint_as_float((unsigned)v);
        }

        float sh  = __shfl_up_sync(0xffffffffu, r1, 1);
        float nb1 = (lane == 0) ? in1 : sh;        // u_{k-1}[i-1]
        float nb2 = (lane == 0) ? prev_in : shp;   // u_{k-2}[i-1]

        // scaled softmin: u = dC + m - lg2(sum ex2(m - u_i))
        float m  = fminf(fminf(nb2, nb1), r1);
        float e0 = ex2f(m - nb2);
        float e1 = ex2f(m - nb1);
        float e2 = ex2f(m - r1);
        float s  = (e0 + e1) + e2;
        float nv = (dd[0] + m) - lg2f_(s);

        shp = sh; prev_in = in1; r1 = nv;

        // publish u_k boundary (tag k+1)
        if (lane == 31) {
            unsigned long long p = (((unsigned long long)(k + 1)) << 32)
                                 | (unsigned long long)__float_as_uint(r1);
            if (pub_ring) {
                const uint32_t pa = prod_base + (((uint32_t)(k + 1) * 8u) & 2047u);
                asm volatile("st.volatile.shared.u64 [%0], %1;" :: "r"(pa), "l"(p) : "memory");
            } else if (pub_dsmem) {
                asm volatile("st.shared::cluster.u64 [%0], %1;"
                             :: "r"(rem_inbox + (uint32_t)(k + 1) * 8u), "l"(p) : "memory");
            }
        }

        // progress + ring backpressure, every 64 diagonals
        if ((k & 63) == 0) {
            if (w > 0 && lane == 0) {
                asm volatile("st.volatile.shared.u32 [%0], %1;" :: "r"(myprog_a), "r"((unsigned)k) : "memory");
            }
            if (pub_ring) {
                unsigned pr;
                do {
                    asm volatile("ld.volatile.shared.u32 %0, [%1];" : "=r"(pr) : "r"(rprog_a));
                } while ((unsigned)k - pr > 160u);
            }
        }

        // rotate prefetch ring (renamed away under unrolling)
#pragma unroll
        for (int q = 0; q < PF - 1; q++) dd[q] = dd[q + 1];
        dd[PF - 1] = dn;
    };

    int k = 1;
#pragma unroll 1
    for (; k + (PF - 1) <= KK - 1; k += PF) {
#pragma unroll
        for (int u = 0; u < PF; u++) body(k + u);
    }
#pragma unroll 1
    for (; k <= KK - 1; ++k) body(k);

    if (rank == 7 && t == 255) g_sdtw[z] = r1 * GLN2;   // rescale back

    asm volatile("barrier.cluster.arrive.aligned;" ::: "memory");
    asm volatile("barrier.cluster.wait.aligned;" ::: "memory");
}

// ---------------- profiling-alignment dummy (keeps ncu's skip-5 capture on softdtw) ----------------
__global__ void dummy_kernel() {}

// ---------------- combine ----------------
__global__ void finalize_kernel(float* out) {
    float pos = g_sdtw[0] - 0.5f * (g_sdtw[1] + g_sdtw[2]);
    float idm = (float)(g_idm[0] + g_idm[1]);
    out[0] = (pos + idm) / 2048.0f;    // ALPHA = 1, NUM_FRAMES = 2048
}

// ---------------- launch ----------------
extern "C" void kernel_launch(void* const* d_in, const int* in_sizes, int n_in,
                              void* d_out, int out_size) {
    const float* a = (const float*)d_in[0];   // a_emb [1,2048,128] fp32
    const float* b = (const float*)d_in[1];   // b_emb [1,2048,128] fp32
    (void)in_sizes; (void)n_in; (void)out_size;

    norms_kernel<<<512, 256>>>(a, b);
    dim3 g(32, 32, 3);
    pairdist_kernel<<<g, 256>>>(a, b);        // D in diagonal layout + fused idm
    dummy_kernel<<<1, 32>>>();                // alignment shim: skip-5 capture hits softdtw
    softdtw_kernel<<<24, 256>>>();            // 3 clusters x 8 CTAs, pipelined wavefronts
    finalize_kernel<<<1, 1>>>((float*)d_out);
}

// round 12
// speedup vs baseline: 2.2488x; 2.2488x over previous
#include <cuda_runtime.h>
#include <cuda_bf16.h>
#include <cstdint>

#define NN 2048
#define KK 4095              // number of anti-diagonals = 2N-1
#define BIGF 1e10f
#define C_EXP 14.4269504088896340f   /* 10 * log2(e)  (1/gamma = 10) */
#define C_LOG 0.0693147180559945f    /* 0.1 * ln(2) */
#define DSK_STRIDE ((size_t)NN)
#define DSK_MAT ((size_t)KK * (size_t)NN)   // 8,386,560 floats per matrix

// ---------------- device scratch (no allocations allowed) ----------------
__device__ float  g_dsk[3 * KK * NN];   // ~100.6 MB, diagonal-major D for xy/xx/yy
__device__ float  g_norms[2 * NN];      // row norms of a (first 2048) and b (next 2048)
__device__ double g_idm[2];             // idm_a, idm_b accumulators
__device__ float  g_sdtw[3];            // softdtw(xy), softdtw(xx), softdtw(yy)

// ---------------- fast math helpers ----------------
__device__ __forceinline__ float ex2f(float x) {
    float y; asm("ex2.approx.ftz.f32 %0, %1;" : "=f"(y) : "f"(x)); return y;
}
__device__ __forceinline__ float lg2f_(float x) {
    float y; asm("lg2.approx.f32 %0, %1;" : "=f"(y) : "f"(x)); return y;
}
__device__ __forceinline__ uint32_t smem_u32(const void* p) {
    uint32_t a;
    asm("{ .reg .u64 t; cvta.to.shared.u64 t, %1; cvt.u32.u64 %0, t; }" : "=r"(a) : "l"(p));
    return a;
}

// ---------------- row norms + accumulator init ----------------
__global__ void norms_kernel(const float* __restrict__ a, const float* __restrict__ b) {
    if (blockIdx.x == 0 && threadIdx.x == 0) { g_idm[0] = 0.0; g_idm[1] = 0.0; }
    int w    = blockIdx.x * (blockDim.x >> 5) + (threadIdx.x >> 5);
    int lane = threadIdx.x & 31;
    if (w >= 2 * NN) return;
    const float* src = (w < NN) ? (a + (size_t)w * 128) : (b + (size_t)(w - NN) * 128);
    float s = 0.0f;
#pragma unroll
    for (int q = 0; q < 4; q++) { float v = src[lane + 32 * q]; s = fmaf(v, v, s); }
#pragma unroll
    for (int off = 16; off; off >>= 1) s += __shfl_xor_sync(0xffffffffu, s, off);
    if (lane == 0) g_norms[w] = s;
}

// ---------------- pairwise sqdist GEMM (R7 scalar version): diagonal-major D + fused idm ----------------
__global__ void __launch_bounds__(256) pairdist_kernel(const float* __restrict__ a,
                                                       const float* __restrict__ b) {
    __shared__ float pool[2 * 64 * 65];   // 33,280 B
    float* xsT = pool;                    // [kk][ii], stride 65 (conflict-free)
    float* ysT = pool + 64 * 65;

    const int z = blockIdx.z;             // 0: (a,b)  1: (a,a)  2: (b,b)
    const float* X  = (z == 2) ? b : a;
    const float* Y  = (z == 0) ? b : ((z == 1) ? a : b);
    const float* xn = g_norms + ((z == 2) ? NN : 0);
    const float* yn = g_norms + ((z == 1) ? 0 : NN);

    const int i0 = blockIdx.y * 64, j0 = blockIdx.x * 64;
    const int tid = threadIdx.x;
    const int tx = tid & 15, ty = tid >> 4;

    float acc[4][4];
#pragma unroll
    for (int r = 0; r < 4; r++)
#pragma unroll
        for (int c = 0; c < 4; c++) acc[r][c] = 0.0f;

    for (int kc = 0; kc < 128; kc += 64) {
        const int kk = tid & 63, ib = tid >> 6;
#pragma unroll
        for (int ii = ib; ii < 64; ii += 4) {
            xsT[kk * 65 + ii] = X[(size_t)(i0 + ii) * 128 + kc + kk];
            ysT[kk * 65 + ii] = Y[(size_t)(j0 + ii) * 128 + kc + kk];
        }
        __syncthreads();
#pragma unroll 4
        for (int k2 = 0; k2 < 64; ++k2) {
            float ra[4], rb[4];
#pragma unroll
            for (int r = 0; r < 4; r++) ra[r] = xsT[k2 * 65 + ty * 4 + r];
#pragma unroll
            for (int c = 0; c < 4; c++) rb[c] = ysT[k2 * 65 + tx * 4 + c];
#pragma unroll
            for (int r = 0; r < 4; r++)
#pragma unroll
                for (int c = 0; c < 4; c++) acc[r][c] = fmaf(ra[r], rb[c], acc[r][c]);
        }
        __syncthreads();
    }

    float xnv[4], ynv[4];
#pragma unroll
    for (int r = 0; r < 4; r++) xnv[r] = xn[i0 + ty * 4 + r];
#pragma unroll
    for (int c = 0; c < 4; c++) ynv[c] = yn[j0 + tx * 4 + c];

    float* ds = pool;                     // reuse; 64 x 66 floats
    float lsum = 0.0f;
    const float inv_n = 1.0f / 2048.0f;
    const float thr   = 10.0f / 2048.0f;  // SIGMA / seq_len (exact in fp32)
#pragma unroll
    for (int r = 0; r < 4; r++) {
#pragma unroll
        for (int c = 0; c < 4; c++) {
            float d = fmaxf(xnv[r] + ynv[c] - 2.0f * acc[r][c], 0.0f);
            ds[(ty * 4 + r) * 66 + tx * 4 + c] = d;
            if (z) {
                int ig = i0 + ty * 4 + r, jg = j0 + tx * 4 + c;
                float gd   = (float)(ig - jg) * inv_n;
                float wgt  = fmaf(gd, gd, 1.0f);
                float diff = fabsf(gd) - thr;
                float prob = fmaxf(2.0f - d, 0.0f);
                lsum += (diff > 0.0f) ? (wgt * prob) : d;
            }
        }
    }
    if (z) {
#pragma unroll
        for (int off = 16; off; off >>= 1) lsum += __shfl_xor_sync(0xffffffffu, lsum, off);
        if ((tid & 31) == 0) atomicAdd(&g_idm[z - 1], (double)lsum);
    }
    __syncthreads();  // ds fully written before diag write-out

    float* dst = g_dsk + (size_t)z * DSK_MAT + (size_t)(i0 + j0) * DSK_STRIDE + i0;
    const int w = tid >> 5, lane = tid & 31;
    for (int d = w; d < 127; d += 8) {
        int lo = max(0, d - 63), hi = min(63, d);
        for (int e = lo + lane; e <= hi; e += 32) {
            dst[(size_t)d * DSK_STRIDE + e] = ds[e * 66 + (d - e)];
        }
    }
}

// ---------------- softDTW: group-handoff wavefront (poll once per 8 diagonals) ----------------
// 3 clusters x 8 CTAs x 256 threads, 1 element/thread. R7 arithmetic & publish; the consumer
// blocks only on the LAST slot of each 8-diagonal group, then batch-reads the other 7
// (self-tagged slots; rare-retry verification). Amortizes spin-wakeup 8x and adds pipeline slack.
#define PF 8
__global__ void __launch_bounds__(256, 1) __cluster_dims__(8, 1, 1)
softdtw_kernel() {
    const int bz   = blockIdx.x;
    const int z    = bz >> 3;            // matrix id
    const int rank = bz & 7;             // segment within cluster
    const float* __restrict__ dsk = g_dsk + (size_t)z * DSK_MAT;
    const int t = threadIdx.x;
    const int lane = t & 31, w = t >> 5;
    const int i = rank * 256 + t;        // global element index on each diagonal

    __shared__ unsigned long long inbox[4096];     // 32 KB, slot k: left CTA's r_{k-1}, tag=k
    __shared__ unsigned long long ring[7][256];    // 14 KB, boundary w -> w+1
    __shared__ unsigned int prog[8];               // consumer progress (for backpressure)

    for (int s = t; s < 4096; s += 256) inbox[s] = 0ULL;
    for (int s = t; s < 7 * 256; s += 256) ((unsigned long long*)ring)[s] = 0ULL;
    if (t < 8) prog[t] = 0u;
    __syncthreads();
    if (t == 0) {   // pre-publish diag-0 boundaries (r_0 at any boundary is BIG)
        unsigned long long p0 = (1ULL << 32) | (unsigned long long)__float_as_uint(BIGF);
        for (int b = 0; b < 7; b++) ring[b][1] = p0;
    }
    __syncthreads();
    asm volatile("barrier.cluster.arrive.aligned;" ::: "memory");
    asm volatile("barrier.cluster.wait.aligned;" ::: "memory");

    const uint32_t inbox_a = smem_u32(inbox);
    const uint32_t ring_a  = smem_u32(ring);
    const uint32_t prog_a  = smem_u32(prog);
    uint32_t rem_inbox = 0;
    if (rank < 7) {
        asm("mapa.shared::cluster.u32 %0, %1, %2;"
            : "=r"(rem_inbox) : "r"(inbox_a), "r"(rank + 1));
    }
    if (t == 255 && rank < 7) {   // cross-CTA pre-publish of diag-0 boundary
        unsigned long long p0 = (1ULL << 32) | (unsigned long long)__float_as_uint(BIGF);
        asm volatile("st.shared::cluster.u64 [%0], %1;" :: "r"(rem_inbox + 8u), "l"(p0) : "memory");
    }

    const bool has_left  = (w > 0) || (rank > 0);
    const bool pub_ring  = (w < 7);
    const bool pub_dsmem = (w == 7) && (rank < 7);
    const uint32_t cons_base = (w == 0) ? inbox_a : (ring_a + (uint32_t)(w - 1) * 2048u);
    const uint32_t cons_mask = (w == 0) ? 0xFFFFFFFFu : 2047u;   // byte-offset mask
    const uint32_t prod_base = ring_a + (uint32_t)w * 2048u;     // valid when w<7
    const uint32_t myprog_a  = prog_a + 4u * (uint32_t)w;
    const uint32_t rprog_a   = prog_a + 4u * (uint32_t)(w + 1);

    // state: r1 = r_{k-1}[i]; shp = r_{k-2}[i-1] (prev shfl); prev_in = boundary r_{k-2}[i-1]
    float r1 = (i == 0) ? dsk[0] : BIGF;
    float shp = BIGF, prev_in = BIGF;

    // D prefetch ring, depth PF; rotation renamed away under unrolling
    float dd[PF];
#pragma unroll
    for (int q = 0; q < PF; q++) {
        int kn = 1 + q;
        dd[q] = (kn <= KK - 1 && kn >= i && kn <= i + (NN - 1))
              ? dsk[(size_t)kn * NN + i] : BIGF;
    }
    const float* __restrict__ prow = dsk + (size_t)(1 + PF) * NN + i;

    // body WITHOUT the poll: left-boundary value supplied by the group read
    auto body = [&](int k, float in1) {
        // prefetch diag k+PF (predicated, coalesced)
        const int kn = k + PF;
        float dn = BIGF;
        if (kn <= KK - 1) {
            if (kn >= i && kn <= i + (NN - 1)) dn = *prow;
        }
        prow += NN;

        float sh  = __shfl_up_sync(0xffffffffu, r1, 1);
        float nb1 = (lane == 0) ? in1 : sh;        // r_{k-1}[i-1]
        float nb2 = (lane == 0) ? prev_in : shp;   // r_{k-2}[i-1]

        // softmin: 3 parallel ex2 off the min pivot
        float m  = fminf(fminf(nb2, nb1), r1);
        float e0 = ex2f((m - nb2) * C_EXP);
        float e1 = ex2f((m - nb1) * C_EXP);
        float e2 = ex2f((m - r1)  * C_EXP);
        float s  = (e0 + e1) + e2;
        float nv = dd[0] + fmaf(-C_LOG, lg2f_(s), m);

        shp = sh; prev_in = in1; r1 = nv;

        // publish r_k boundary (tag k+1) — unchanged from R7
        if (lane == 31) {
            unsigned long long p = (((unsigned long long)(k + 1)) << 32)
                                 | (unsigned long long)__float_as_uint(r1);
            if (pub_ring) {
                const uint32_t pa = prod_base + (((uint32_t)(k + 1) * 8u) & 2047u);
                asm volatile("st.volatile.shared.u64 [%0], %1;" :: "r"(pa), "l"(p) : "memory");
            } else if (pub_dsmem) {
                asm volatile("st.shared::cluster.u64 [%0], %1;"
                             :: "r"(rem_inbox + (uint32_t)(k + 1) * 8u), "l"(p) : "memory");
            }
        }

        // rotate prefetch ring (renamed away under unrolling)
#pragma unroll
        for (int q = 0; q < PF - 1; q++) dd[q] = dd[q + 1];
        dd[PF - 1] = dn;
    };

    // read one boundary slot with its own verify-retry (used for tail diagonals)
    auto read_slot = [&](int k) -> float {
        float in1 = BIGF;
        if (has_left) {
            unsigned long long v;
            const uint32_t addr = cons_base + (((uint32_t)k * 8u) & cons_mask);
            do {
                asm volatile("ld.volatile.shared.u64 %0, [%1];" : "=l"(v) : "r"(addr));
            } while ((unsigned)(v >> 32) != (unsigned)k);
            in1 = __uint_as_float((unsigned)v);
        }
        return in1;
    };

    int k = 1;
#pragma unroll 1
    for (; k + (PF - 1) <= KK - 1; k += PF) {
        // progress publish + rare ring backpressure (window 160+64+8 < 256 slots)
        if ((k & 63) == 1) {
            if (w > 0 && lane == 0) {
                asm volatile("st.volatile.shared.u32 [%0], %1;" :: "r"(myprog_a), "r"((unsigned)k) : "memory");
            }
            if (pub_ring) {
                unsigned pr;
                do {
                    asm volatile("ld.volatile.shared.u32 %0, [%1];" : "=r"(pr) : "r"(rprog_a));
                } while ((unsigned)k - pr > 160u);
            }
        }

        // ---- group poll: block on the LAST slot, then batch-verify the rest ----
        float in1v[PF];
        if (has_left) {
            unsigned long long v;
            const uint32_t alast = cons_base + (((uint32_t)(k + PF - 1) * 8u) & cons_mask);
            do {
                asm volatile("ld.volatile.shared.u64 %0, [%1];" : "=l"(v) : "r"(alast));
            } while ((unsigned)(v >> 32) != (unsigned)(k + PF - 1));
            in1v[PF - 1] = __uint_as_float((unsigned)v);
            bool ok;
            do {
                ok = true;
#pragma unroll
                for (int u = 0; u < PF - 1; u++) {
                    unsigned long long vv;
                    const uint32_t au = cons_base + (((uint32_t)(k + u) * 8u) & cons_mask);
                    asm volatile("ld.volatile.shared.u64 %0, [%1];" : "=l"(vv) : "r"(au));
                    in1v[u] = __uint_as_float((unsigned)vv);
                    ok = ok && ((unsigned)(vv >> 32) == (unsigned)(k + u));
                }
            } while (!ok);
        } else {
#pragma unroll
            for (int u = 0; u < PF; u++) in1v[u] = BIGF;
        }

#pragma unroll
        for (int u = 0; u < PF; u++) body(k + u, in1v[u]);
    }
#pragma unroll 1
    for (; k <= KK - 1; ++k) body(k, read_slot(k));   // 6-diagonal tail, per-diag poll

    if (rank == 7 && t == 255) g_sdtw[z] = r1;   // r_{K-1}[N-1]

    asm volatile("barrier.cluster.arrive.aligned;" ::: "memory");
    asm volatile("barrier.cluster.wait.aligned;" ::: "memory");
}

// ---------------- profiling-alignment dummy (keeps ncu's skip-5 capture on softdtw) ----------------
__global__ void dummy_kernel() {}

// ---------------- combine ----------------
__global__ void finalize_kernel(float* out) {
    float pos = g_sdtw[0] - 0.5f * (g_sdtw[1] + g_sdtw[2]);
    float idm = (float)(g_idm[0] + g_idm[1]);
    out[0] = (pos + idm) / 2048.0f;    // ALPHA = 1, NUM_FRAMES = 2048
}

// ---------------- launch ----------------
extern "C" void kernel_launch(void* const* d_in, const int* in_sizes, int n_in,
                              void* d_out, int out_size) {
    const float* a = (const float*)d_in[0];   // a_emb [1,2048,128] fp32
    const float* b = (const float*)d_in[1];   // b_emb [1,2048,128] fp32
    (void)in_sizes; (void)n_in; (void)out_size;

    norms_kernel<<<512, 256>>>(a, b);
    dim3 g(32, 32, 3);
    pairdist_kernel<<<g, 256>>>(a, b);        // D in diagonal layout + fused idm
    dummy_kernel<<<1, 32>>>();                // alignment shim: skip-5 capture hits softdtw
    softdtw_kernel<<<24, 256>>>();            // 3 clusters x 8 CTAs, group-handoff wavefronts
    finalize_kernel<<<1, 1>>>((float*)d_out);
}